// round 1
// baseline (speedup 1.0000x reference)
#include <cuda_runtime.h>
#include <math.h>

// Problem constants
#define BN 64
#define SN 128
#define DN 128
#define VN 512
#define CN 256
#define NNM 256   // memory slots N
#define MN 64     // memory width M
#define NT 512    // threads per CTA

// SMEM layout (float offsets). mem padded to stride 65 for conflict-free
// row AND column access. All other arrays 16B-aligned for float4 LDS.
#define MEM_OFF   0
#define MEM_STR   65
#define H_OFF     16640
#define C_OFF     16896
#define G_OFF     17152
#define CI_OFF    18176
#define RV_OFF    18368
#define RW_OFF    18432
#define WG_OFF    18688
#define WW_OFF    18944
#define KEY_OFF   19200
#define ER_OFF    19264
#define AD_OFF    19328
#define RED_OFF   19392
#define SCAL_OFF  19408
#define SMEM_FLOATS 19424
// scal indices
#define SC_BETA 0
#define SC_GATE 1
#define SC_GAMMA 2
#define SC_SH0 3
#define SC_SH1 4
#define SC_SH2 5
#define SC_KN 6

__device__ __forceinline__ float sigf(float x) { return 1.0f / (1.0f + expf(-x)); }
__device__ __forceinline__ float softplusf(float x) {
    // stable: max(x,0) + log1p(exp(-|x|))
    return fmaxf(x, 0.0f) + log1pf(expf(-fabsf(x)));
}

__device__ __forceinline__ float blockReduceSum(float v, float* red) {
    #pragma unroll
    for (int o = 16; o; o >>= 1) v += __shfl_down_sync(0xffffffffu, v, o);
    int wid = threadIdx.x >> 5, lane = threadIdx.x & 31;
    __syncthreads();                 // protect scratch from previous use
    if (lane == 0) red[wid] = v;
    __syncthreads();
    if (wid == 0) {
        v = (lane < (NT / 32)) ? red[lane] : 0.0f;
        #pragma unroll
        for (int o = 8; o; o >>= 1) v += __shfl_down_sync(0xffffffffu, v, o);
        if (lane == 0) red[0] = v;
    }
    __syncthreads();
    return red[0];
}

__device__ __forceinline__ float blockReduceMax(float v, float* red) {
    #pragma unroll
    for (int o = 16; o; o >>= 1) v = fmaxf(v, __shfl_down_sync(0xffffffffu, v, o));
    int wid = threadIdx.x >> 5, lane = threadIdx.x & 31;
    __syncthreads();
    if (lane == 0) red[wid] = v;
    __syncthreads();
    if (wid == 0) {
        v = (lane < (NT / 32)) ? red[lane] : -INFINITY;
        #pragma unroll
        for (int o = 8; o; o >>= 1) v = fmaxf(v, __shfl_down_sync(0xffffffffu, v, o));
        if (lane == 0) red[0] = v;
    }
    __syncthreads();
    return red[0];
}

extern __shared__ float sm[];

__global__ void __launch_bounds__(NT, 1) ntm_kernel(
    const int*   __restrict__ x,
    const float* __restrict__ emb,
    const float* __restrict__ W_ih,
    const float* __restrict__ W_hh,
    const float* __restrict__ b_ih,
    const float* __restrict__ b_hh,
    const float* __restrict__ key_W,
    const float* __restrict__ key_b,
    const float* __restrict__ beta_W,
    const float* __restrict__ beta_b,
    const float* __restrict__ gate_W,
    const float* __restrict__ gate_b,
    const float* __restrict__ shift_W,
    const float* __restrict__ shift_b,
    const float* __restrict__ gamma_W,
    const float* __restrict__ gamma_b,
    const float* __restrict__ erase_W,
    const float* __restrict__ erase_b,
    const float* __restrict__ add_W,
    const float* __restrict__ add_b,
    const float* __restrict__ out_W,
    const float* __restrict__ out_b,
    const float* __restrict__ mem_init,
    float*       __restrict__ out)
{
    const int t = threadIdx.x;
    const int b = blockIdx.x;

    // ---- init state ----
    for (int i = t; i < NNM * MN; i += NT) {
        int n = i >> 6, m = i & 63;
        sm[MEM_OFF + n * MEM_STR + m] = mem_init[(b * NNM + n) * MN + m];
    }
    for (int i = t; i < CN; i += NT) { sm[H_OFF + i] = 0.0f; sm[C_OFF + i] = 0.0f; }
    for (int i = t; i < NNM; i += NT) sm[RW_OFF + i] = 0.0f;
    for (int i = t; i < MN;  i += NT) sm[RV_OFF + i] = 0.0f;
    __syncthreads();

    for (int s = 0; s < SN; s++) {
        // ---- A: build ci = [emb[x], rv] ----
        if (t < DN) {
            int xi = x[b * SN + s];
            sm[CI_OFF + t] = emb[xi * DN + t];
        } else if (t < DN + MN) {
            sm[CI_OFF + t] = sm[RV_OFF + (t - DN)];
        }
        __syncthreads();

        // ---- B: gates = ci@W_ih^T + h@W_hh^T + b_ih + b_hh ----
        {
            const float4* ci4 = (const float4*)(sm + CI_OFF);
            const float4* h4  = (const float4*)(sm + H_OFF);
            #pragma unroll
            for (int jj = 0; jj < 2; jj++) {
                int j = t + jj * NT;
                float acc = b_ih[j] + b_hh[j];
                const float4* wi = (const float4*)(W_ih + j * (DN + MN));
                #pragma unroll 8
                for (int k = 0; k < (DN + MN) / 4; k++) {
                    float4 wv = wi[k]; float4 cv = ci4[k];
                    acc = fmaf(wv.x, cv.x, acc); acc = fmaf(wv.y, cv.y, acc);
                    acc = fmaf(wv.z, cv.z, acc); acc = fmaf(wv.w, cv.w, acc);
                }
                const float4* wh = (const float4*)(W_hh + j * CN);
                #pragma unroll 8
                for (int k = 0; k < CN / 4; k++) {
                    float4 wv = wh[k]; float4 hv = h4[k];
                    acc = fmaf(wv.x, hv.x, acc); acc = fmaf(wv.y, hv.y, acc);
                    acc = fmaf(wv.z, hv.z, acc); acc = fmaf(wv.w, hv.w, acc);
                }
                sm[G_OFF + j] = acc;
            }
        }
        __syncthreads();

        // ---- C: LSTM pointwise (torch order i,f,g,o) ----
        if (t < CN) {
            float ig = sm[G_OFF + t];
            float fg = sm[G_OFF + CN + t];
            float gg = sm[G_OFF + 2 * CN + t];
            float og = sm[G_OFF + 3 * CN + t];
            float cc = sigf(fg) * sm[C_OFF + t] + sigf(ig) * tanhf(gg);
            sm[C_OFF + t] = cc;
            sm[H_OFF + t] = sigf(og) * tanhf(cc);
        }
        __syncthreads();

        // ---- D: head projections (198 rows x 256) ----
        if (t < 198) {
            const float* wr; float bias;
            if (t < 64)        { wr = key_W   + t * CN;          bias = key_b[t]; }
            else if (t == 64)  { wr = beta_W;                    bias = beta_b[0]; }
            else if (t == 65)  { wr = gate_W;                    bias = gate_b[0]; }
            else if (t < 69)   { wr = shift_W + (t - 66) * CN;   bias = shift_b[t - 66]; }
            else if (t == 69)  { wr = gamma_W;                   bias = gamma_b[0]; }
            else if (t < 134)  { wr = erase_W + (t - 70) * CN;   bias = erase_b[t - 70]; }
            else               { wr = add_W   + (t - 134) * CN;  bias = add_b[t - 134]; }
            const float4* w4 = (const float4*)wr;
            const float4* h4 = (const float4*)(sm + H_OFF);
            float acc = bias;
            #pragma unroll 8
            for (int k = 0; k < CN / 4; k++) {
                float4 wv = w4[k]; float4 hv = h4[k];
                acc = fmaf(wv.x, hv.x, acc); acc = fmaf(wv.y, hv.y, acc);
                acc = fmaf(wv.z, hv.z, acc); acc = fmaf(wv.w, hv.w, acc);
            }
            if (t < 64)        sm[KEY_OFF + t] = acc;
            else if (t == 64)  sm[SCAL_OFF + SC_BETA]  = softplusf(acc);
            else if (t == 65)  sm[SCAL_OFF + SC_GATE]  = sigf(acc);
            else if (t < 69)   sm[SCAL_OFF + SC_SH0 + (t - 66)] = acc;  // raw shift
            else if (t == 69)  sm[SCAL_OFF + SC_GAMMA] = 1.0f + softplusf(acc);
            else if (t < 134)  sm[ER_OFF + (t - 70)]  = sigf(acc);
            else               sm[AD_OFF + (t - 134)] = tanhf(acc);
        }
        __syncthreads();

        // ---- D2: key norm (warp 0) + shift softmax (thread 32) ----
        if (t < 32) {
            float k0 = sm[KEY_OFF + t], k1 = sm[KEY_OFF + t + 32];
            float sq = k0 * k0 + k1 * k1;
            #pragma unroll
            for (int o = 16; o; o >>= 1) sq += __shfl_down_sync(0xffffffffu, sq, o);
            if (t == 0) sm[SCAL_OFF + SC_KN] = fmaxf(sqrtf(sq), 1e-12f);
        } else if (t == 32) {
            float a0 = sm[SCAL_OFF + SC_SH0], a1 = sm[SCAL_OFF + SC_SH1], a2 = sm[SCAL_OFF + SC_SH2];
            float mx = fmaxf(a0, fmaxf(a1, a2));
            float e0 = expf(a0 - mx), e1 = expf(a1 - mx), e2 = expf(a2 - mx);
            float si = e0 + e1 + e2;
            sm[SCAL_OFF + SC_SH0] = e0 / si;
            sm[SCAL_OFF + SC_SH1] = e1 / si;
            sm[SCAL_OFF + SC_SH2] = e2 / si;
        }
        __syncthreads();

        // ---- E: content addressing + gate + shift + sharpen ----
        {
            float beta  = sm[SCAL_OFF + SC_BETA];
            float gate  = sm[SCAL_OFF + SC_GATE];
            float gamma = sm[SCAL_OFF + SC_GAMMA];
            float kn    = sm[SCAL_OFF + SC_KN];
            float a = -INFINITY;
            if (t < NNM) {
                float dot = 0.0f, nrm = 0.0f;
                #pragma unroll 8
                for (int m = 0; m < MN; m++) {
                    float mv = sm[MEM_OFF + t * MEM_STR + m];
                    dot = fmaf(mv, sm[KEY_OFF + m], dot);
                    nrm = fmaf(mv, mv, nrm);
                }
                float sim = dot / (fmaxf(sqrtf(nrm), 1e-12f) * kn);
                a = beta * sim;
            }
            float amax = blockReduceMax(a, sm + RED_OFF);
            float e = (t < NNM) ? expf(a - amax) : 0.0f;
            float denom = blockReduceSum(e, sm + RED_OFF);
            if (t < NNM) {
                sm[WG_OFF + t] = gate * (e / denom) + (1.0f - gate) * sm[RW_OFF + t];
            }
            __syncthreads();
            float sh0 = sm[SCAL_OFF + SC_SH0];
            float sh1 = sm[SCAL_OFF + SC_SH1];
            float sh2 = sm[SCAL_OFF + SC_SH2];
            float ws = 0.0f;
            if (t < NNM) {
                float wv = sh0 * sm[WG_OFF + ((t + 1) & 255)]
                         + sh1 * sm[WG_OFF + t]
                         + sh2 * sm[WG_OFF + ((t + 255) & 255)];
                ws = powf(wv, gamma);
            }
            float wsum = blockReduceSum(ws, sm + RED_OFF);
            if (t < NNM) {
                float wn = ws / wsum;
                sm[WW_OFF + t] = wn;
                sm[RW_OFF + t] = wn;   // rw for next step
            }
        }
        __syncthreads();

        // ---- F: rv = w @ mem (read BEFORE write) ----
        {
            int m = t >> 3, r = t & 7;   // 8 threads per m-column
            float acc = 0.0f;
            for (int n = r; n < NNM; n += 8)
                acc = fmaf(sm[WW_OFF + n], sm[MEM_OFF + n * MEM_STR + m], acc);
            #pragma unroll
            for (int o = 4; o; o >>= 1) acc += __shfl_down_sync(0xffffffffu, acc, o, 8);
            if (r == 0) sm[RV_OFF + m] = acc;
        }
        __syncthreads();

        // ---- mem update: mem = mem*(1 - w⊗er) + w⊗ad ----
        for (int i = t; i < NNM * MN; i += NT) {
            int n = i >> 6, m = i & 63;
            float wv = sm[WW_OFF + n];
            float* p = &sm[MEM_OFF + n * MEM_STR + m];
            *p = (*p) * (1.0f - wv * sm[ER_OFF + m]) + wv * sm[AD_OFF + m];
        }
        __syncthreads();

        // ---- G: logits = [h, rv] @ out_W^T + out_b ----
        {
            float acc = out_b[t];
            const float4* w4 = (const float4*)(out_W + t * (CN + MN));
            const float4* h4 = (const float4*)(sm + H_OFF);
            #pragma unroll 8
            for (int k = 0; k < CN / 4; k++) {
                float4 wv = w4[k]; float4 hv = h4[k];
                acc = fmaf(wv.x, hv.x, acc); acc = fmaf(wv.y, hv.y, acc);
                acc = fmaf(wv.z, hv.z, acc); acc = fmaf(wv.w, hv.w, acc);
            }
            const float4* r4 = (const float4*)(sm + RV_OFF);
            #pragma unroll
            for (int k = 0; k < MN / 4; k++) {
                float4 wv = w4[CN / 4 + k]; float4 rv4 = r4[k];
                acc = fmaf(wv.x, rv4.x, acc); acc = fmaf(wv.y, rv4.y, acc);
                acc = fmaf(wv.z, rv4.z, acc); acc = fmaf(wv.w, rv4.w, acc);
            }
            out[((size_t)b * SN + s) * VN + t] = acc;
        }
        __syncthreads();
    }
}

extern "C" void kernel_launch(void* const* d_in, const int* in_sizes, int n_in,
                              void* d_out, int out_size) {
    const int*   x        = (const int*)  d_in[0];
    const float* emb      = (const float*)d_in[1];
    const float* W_ih     = (const float*)d_in[2];
    const float* W_hh     = (const float*)d_in[3];
    const float* b_ih     = (const float*)d_in[4];
    const float* b_hh     = (const float*)d_in[5];
    const float* key_W    = (const float*)d_in[6];
    const float* key_b    = (const float*)d_in[7];
    const float* beta_W   = (const float*)d_in[8];
    const float* beta_b   = (const float*)d_in[9];
    const float* gate_W   = (const float*)d_in[10];
    const float* gate_b   = (const float*)d_in[11];
    const float* shift_W  = (const float*)d_in[12];
    const float* shift_b  = (const float*)d_in[13];
    const float* gamma_W  = (const float*)d_in[14];
    const float* gamma_b  = (const float*)d_in[15];
    const float* erase_W  = (const float*)d_in[16];
    const float* erase_b  = (const float*)d_in[17];
    const float* add_W    = (const float*)d_in[18];
    const float* add_b    = (const float*)d_in[19];
    const float* out_W    = (const float*)d_in[20];
    const float* out_b    = (const float*)d_in[21];
    const float* mem_init = (const float*)d_in[22];
    float* out = (float*)d_out;

    size_t smem_bytes = SMEM_FLOATS * sizeof(float);
    cudaFuncSetAttribute(ntm_kernel, cudaFuncAttributeMaxDynamicSharedMemorySize,
                         (int)smem_bytes);
    ntm_kernel<<<BN, NT, smem_bytes>>>(
        x, emb, W_ih, W_hh, b_ih, b_hh,
        key_W, key_b, beta_W, beta_b, gate_W, gate_b,
        shift_W, shift_b, gamma_W, gamma_b,
        erase_W, erase_b, add_W, add_b,
        out_W, out_b, mem_init, out);
}

// round 2
// speedup vs baseline: 4.1858x; 4.1858x over previous
#include <cuda_runtime.h>
#include <math.h>

// Problem constants
#define BN 64
#define SN 128
#define DN 128
#define VN 512
#define CN 256
#define NNM 256   // memory slots N
#define MN 64     // memory width M
#define NT 512    // threads per CTA

#define KG 448            // gates GEMV k (192 + 256)
#define KG4 (KG/4)        // 112
#define KH4 (CN/4)        // 64
#define KO 320            // out GEMV k (256 + 64)
#define KO4 (KO/4)        // 80
#define NHEAD 198

// Transposed weight panels (filled by prep kernel each launch)
__device__ float4 g_Wg[KG4 * 1024];    // gates:  [kk][row]  1.75MB
__device__ float4 g_Wh[KH4 * NHEAD];   // heads:  [kk][row]
__device__ float4 g_Wo[KO4 * VN];      // out:    [kk][row]
__device__ float  g_gb[1024];          // b_ih + b_hh
__device__ float  g_hb[NHEAD];         // head biases

// ---------------- SMEM layout (float offsets) ----------------
#define MEM_OFF   0
#define MEM_STR   65
#define AV_OFF    16640   // [ci(192) | h(256) | rv(64)] = 512 floats
#define AV_CI     (AV_OFF)
#define AV_RVIN   (AV_OFF + 128)
#define AV_H      (AV_OFF + 192)
#define AV_RV     (AV_OFF + 448)
#define C_OFF     17152
#define G_OFF     17408
#define KEY_OFF   18432
#define ER_OFF    18496
#define AD_OFF    18560
#define RW_OFF    18624
#define WG_OFF    18880
#define WW_OFF    19136
#define RED_OFF   19392
#define SCAL_OFF  19412
#define SMEM_FLOATS 19424
// scal indices
#define SC_BETA 0
#define SC_GATE 1
#define SC_GAMMA 2
#define SC_SH0 3
#define SC_SH1 4
#define SC_SH2 5
#define SC_KN 6

__device__ __forceinline__ float sigf(float x) { return 1.0f / (1.0f + expf(-x)); }
__device__ __forceinline__ float softplusf(float x) {
    return fmaxf(x, 0.0f) + log1pf(expf(-fabsf(x)));
}

__device__ __forceinline__ float blockReduceSum(float v, float* red) {
    #pragma unroll
    for (int o = 16; o; o >>= 1) v += __shfl_down_sync(0xffffffffu, v, o);
    int wid = threadIdx.x >> 5, lane = threadIdx.x & 31;
    __syncthreads();
    if (lane == 0) red[wid] = v;
    __syncthreads();
    if (wid == 0) {
        v = (lane < (NT / 32)) ? red[lane] : 0.0f;
        #pragma unroll
        for (int o = 8; o; o >>= 1) v += __shfl_down_sync(0xffffffffu, v, o);
        if (lane == 0) red[0] = v;
    }
    __syncthreads();
    return red[0];
}

__device__ __forceinline__ float blockReduceMax(float v, float* red) {
    #pragma unroll
    for (int o = 16; o; o >>= 1) v = fmaxf(v, __shfl_down_sync(0xffffffffu, v, o));
    int wid = threadIdx.x >> 5, lane = threadIdx.x & 31;
    __syncthreads();
    if (lane == 0) red[wid] = v;
    __syncthreads();
    if (wid == 0) {
        v = (lane < (NT / 32)) ? red[lane] : -INFINITY;
        #pragma unroll
        for (int o = 8; o; o >>= 1) v = fmaxf(v, __shfl_down_sync(0xffffffffu, v, o));
        if (lane == 0) red[0] = v;
    }
    __syncthreads();
    return red[0];
}

// ================= prep: build transposed weight panels =================
#define NP_WG (KG4 * 1024)
#define NP_WH (KH4 * NHEAD)
#define NP_WO (KO4 * VN)
#define NP_GB 1024
#define NP_HB NHEAD
#define NP_TOTAL (NP_WG + NP_WH + NP_WO + NP_GB + NP_HB)

__global__ void prep_kernel(
    const float* __restrict__ W_ih, const float* __restrict__ W_hh,
    const float* __restrict__ b_ih, const float* __restrict__ b_hh,
    const float* __restrict__ key_W, const float* __restrict__ key_b,
    const float* __restrict__ beta_W, const float* __restrict__ beta_b,
    const float* __restrict__ gate_W, const float* __restrict__ gate_b,
    const float* __restrict__ shift_W, const float* __restrict__ shift_b,
    const float* __restrict__ gamma_W, const float* __restrict__ gamma_b,
    const float* __restrict__ erase_W, const float* __restrict__ erase_b,
    const float* __restrict__ add_W, const float* __restrict__ add_b,
    const float* __restrict__ out_W)
{
    int idx = blockIdx.x * blockDim.x + threadIdx.x;
    if (idx < NP_WG) {
        int kk = idx >> 10, j = idx & 1023;
        int k = kk * 4;
        float4 v;
        if (k < 192) v = *(const float4*)(W_ih + j * 192 + k);
        else         v = *(const float4*)(W_hh + j * 256 + (k - 192));
        g_Wg[idx] = v;
        return;
    }
    idx -= NP_WG;
    if (idx < NP_WH) {
        int kk = idx / NHEAD, j = idx % NHEAD;
        const float* wr;
        if (j < 64)        wr = key_W   + j * CN;
        else if (j == 64)  wr = beta_W;
        else if (j == 65)  wr = gate_W;
        else if (j < 69)   wr = shift_W + (j - 66) * CN;
        else if (j == 69)  wr = gamma_W;
        else if (j < 134)  wr = erase_W + (j - 70) * CN;
        else               wr = add_W   + (j - 134) * CN;
        g_Wh[idx] = *(const float4*)(wr + kk * 4);
        return;
    }
    idx -= NP_WH;
    if (idx < NP_WO) {
        int kk = idx >> 9, j = idx & 511;
        g_Wo[idx] = *(const float4*)(out_W + j * KO + kk * 4);
        return;
    }
    idx -= NP_WO;
    if (idx < NP_GB) { g_gb[idx] = b_ih[idx] + b_hh[idx]; return; }
    idx -= NP_GB;
    if (idx < NP_HB) {
        int j = idx;
        float bias;
        if (j < 64)        bias = key_b[j];
        else if (j == 64)  bias = beta_b[0];
        else if (j == 65)  bias = gate_b[0];
        else if (j < 69)   bias = shift_b[j - 66];
        else if (j == 69)  bias = gamma_b[0];
        else if (j < 134)  bias = erase_b[j - 70];
        else               bias = add_b[j - 134];
        g_hb[j] = bias;
    }
}

// ================= main persistent kernel: 1 CTA per batch =================
extern __shared__ float sm[];

__global__ void __launch_bounds__(NT, 1) ntm_kernel(
    const int*   __restrict__ x,
    const float* __restrict__ emb,
    const float* __restrict__ out_b,
    const float* __restrict__ mem_init,
    float*       __restrict__ out)
{
    const int t = threadIdx.x;
    const int b = blockIdx.x;

    // ---- init state ----
    for (int i = t; i < NNM * MN; i += NT) {
        int n = i >> 6, m = i & 63;
        sm[MEM_OFF + n * MEM_STR + m] = mem_init[(b * NNM + n) * MN + m];
    }
    for (int i = t; i < 512; i += NT) sm[AV_OFF + i] = 0.0f;    // ci|h|rv all zero
    for (int i = t; i < CN; i += NT) sm[C_OFF + i] = 0.0f;
    for (int i = t; i < NNM; i += NT) sm[RW_OFF + i] = 0.0f;
    __syncthreads();

    // per-thread loop-invariant constants
    const float gb0 = g_gb[t];
    const float gb1 = g_gb[t + 512];
    const float obr = out_b[t];
    float hbr = 0.0f;
    if (t < NHEAD) hbr = g_hb[t];

    for (int s = 0; s < SN; s++) {
        // ---- A: build ci = [emb[x], rv_prev] ----
        if (t < MN) {
            sm[AV_RVIN + t] = sm[AV_RV + t];
        } else if (t >= 64 && t < 64 + DN) {
            int tt = t - 64;
            int xi = x[b * SN + s];
            sm[AV_CI + tt] = emb[xi * DN + tt];
        }
        __syncthreads();

        // ---- B: gates = av[0:448) @ Wg^T + gb  (coalesced transposed panel) ----
        {
            const float4* av4 = (const float4*)(sm + AV_OFF);
            float4 a0 = make_float4(0.f, 0.f, 0.f, 0.f);
            float4 a1 = make_float4(0.f, 0.f, 0.f, 0.f);
            #pragma unroll 4
            for (int kk = 0; kk < KG4; kk++) {
                float4 av = av4[kk];
                float4 w0 = g_Wg[kk * 1024 + t];
                float4 w1 = g_Wg[kk * 1024 + 512 + t];
                a0.x = fmaf(w0.x, av.x, a0.x); a0.y = fmaf(w0.y, av.y, a0.y);
                a0.z = fmaf(w0.z, av.z, a0.z); a0.w = fmaf(w0.w, av.w, a0.w);
                a1.x = fmaf(w1.x, av.x, a1.x); a1.y = fmaf(w1.y, av.y, a1.y);
                a1.z = fmaf(w1.z, av.z, a1.z); a1.w = fmaf(w1.w, av.w, a1.w);
            }
            sm[G_OFF + t]       = gb0 + (a0.x + a0.y) + (a0.z + a0.w);
            sm[G_OFF + 512 + t] = gb1 + (a1.x + a1.y) + (a1.z + a1.w);
        }
        __syncthreads();

        // ---- C: LSTM pointwise (torch order i,f,g,o) ----
        if (t < CN) {
            float ig = sm[G_OFF + t];
            float fg = sm[G_OFF + CN + t];
            float gg = sm[G_OFF + 2 * CN + t];
            float og = sm[G_OFF + 3 * CN + t];
            float cc = sigf(fg) * sm[C_OFF + t] + sigf(ig) * tanhf(gg);
            sm[C_OFF + t] = cc;
            sm[AV_H + t] = sigf(og) * tanhf(cc);
        }
        __syncthreads();

        // ---- D: head projections (198 rows x 256), coalesced panel ----
        if (t < NHEAD) {
            const float4* h4 = (const float4*)(sm + AV_H);
            float4 a = make_float4(0.f, 0.f, 0.f, 0.f);
            #pragma unroll 4
            for (int kk = 0; kk < KH4; kk++) {
                float4 hv = h4[kk];
                float4 w = g_Wh[kk * NHEAD + t];
                a.x = fmaf(w.x, hv.x, a.x); a.y = fmaf(w.y, hv.y, a.y);
                a.z = fmaf(w.z, hv.z, a.z); a.w = fmaf(w.w, hv.w, a.w);
            }
            float acc = hbr + (a.x + a.y) + (a.z + a.w);
            if (t < 64)        sm[KEY_OFF + t] = acc;
            else if (t == 64)  sm[SCAL_OFF + SC_BETA]  = softplusf(acc);
            else if (t == 65)  sm[SCAL_OFF + SC_GATE]  = sigf(acc);
            else if (t < 69)   sm[SCAL_OFF + SC_SH0 + (t - 66)] = acc;
            else if (t == 69)  sm[SCAL_OFF + SC_GAMMA] = 1.0f + softplusf(acc);
            else if (t < 134)  sm[ER_OFF + (t - 70)]  = sigf(acc);
            else               sm[AD_OFF + (t - 134)] = tanhf(acc);
        }
        __syncthreads();

        // ---- D2: key norm (warp 0) + shift softmax (thread 32) ----
        if (t < 32) {
            float k0 = sm[KEY_OFF + t], k1 = sm[KEY_OFF + t + 32];
            float sq = k0 * k0 + k1 * k1;
            #pragma unroll
            for (int o = 16; o; o >>= 1) sq += __shfl_down_sync(0xffffffffu, sq, o);
            if (t == 0) sm[SCAL_OFF + SC_KN] = fmaxf(sqrtf(sq), 1e-12f);
        } else if (t == 32) {
            float a0 = sm[SCAL_OFF + SC_SH0], a1 = sm[SCAL_OFF + SC_SH1], a2 = sm[SCAL_OFF + SC_SH2];
            float mx = fmaxf(a0, fmaxf(a1, a2));
            float e0 = expf(a0 - mx), e1 = expf(a1 - mx), e2 = expf(a2 - mx);
            float si = e0 + e1 + e2;
            sm[SCAL_OFF + SC_SH0] = e0 / si;
            sm[SCAL_OFF + SC_SH1] = e1 / si;
            sm[SCAL_OFF + SC_SH2] = e2 / si;
        }
        __syncthreads();

        // ---- E: content addressing + gate + shift + sharpen ----
        {
            float beta  = sm[SCAL_OFF + SC_BETA];
            float gate  = sm[SCAL_OFF + SC_GATE];
            float gamma = sm[SCAL_OFF + SC_GAMMA];
            float kn    = sm[SCAL_OFF + SC_KN];
            float a = -INFINITY;
            if (t < NNM) {
                float dot = 0.0f, nrm = 0.0f;
                #pragma unroll 8
                for (int m = 0; m < MN; m++) {
                    float mv = sm[MEM_OFF + t * MEM_STR + m];
                    dot = fmaf(mv, sm[KEY_OFF + m], dot);
                    nrm = fmaf(mv, mv, nrm);
                }
                float sim = dot / (fmaxf(sqrtf(nrm), 1e-12f) * kn);
                a = beta * sim;
            }
            float amax = blockReduceMax(a, sm + RED_OFF);
            float e = (t < NNM) ? expf(a - amax) : 0.0f;
            float denom = blockReduceSum(e, sm + RED_OFF);
            if (t < NNM) {
                sm[WG_OFF + t] = gate * (e / denom) + (1.0f - gate) * sm[RW_OFF + t];
            }
            __syncthreads();
            float sh0 = sm[SCAL_OFF + SC_SH0];
            float sh1 = sm[SCAL_OFF + SC_SH1];
            float sh2 = sm[SCAL_OFF + SC_SH2];
            float ws = 0.0f;
            if (t < NNM) {
                float wv = sh0 * sm[WG_OFF + ((t + 1) & 255)]
                         + sh1 * sm[WG_OFF + t]
                         + sh2 * sm[WG_OFF + ((t + 255) & 255)];
                ws = powf(wv, gamma);
            }
            float wsum = blockReduceSum(ws, sm + RED_OFF);
            if (t < NNM) {
                float wn = ws / wsum;
                sm[WW_OFF + t] = wn;
                sm[RW_OFF + t] = wn;
            }
        }
        __syncthreads();

        // ---- F: rv = w @ mem (read BEFORE write) ----
        {
            int m = t >> 3, r = t & 7;
            float acc = 0.0f;
            for (int n = r; n < NNM; n += 8)
                acc = fmaf(sm[WW_OFF + n], sm[MEM_OFF + n * MEM_STR + m], acc);
            #pragma unroll
            for (int o = 4; o; o >>= 1) acc += __shfl_down_sync(0xffffffffu, acc, o, 8);
            if (r == 0) sm[AV_RV + m] = acc;
        }
        __syncthreads();

        // ---- mem update ----
        for (int i = t; i < NNM * MN; i += NT) {
            int n = i >> 6, m = i & 63;
            float wv = sm[WW_OFF + n];
            float* p = &sm[MEM_OFF + n * MEM_STR + m];
            *p = (*p) * (1.0f - wv * sm[ER_OFF + m]) + wv * sm[AD_OFF + m];
        }

        // ---- G: logits = av[192:512) @ Wo^T + out_b  (h|rv contiguous) ----
        {
            const float4* hv4 = (const float4*)(sm + AV_H);
            float4 a = make_float4(0.f, 0.f, 0.f, 0.f);
            #pragma unroll 4
            for (int kk = 0; kk < KO4; kk++) {
                float4 hv = hv4[kk];
                float4 w = g_Wo[kk * VN + t];
                a.x = fmaf(w.x, hv.x, a.x); a.y = fmaf(w.y, hv.y, a.y);
                a.z = fmaf(w.z, hv.z, a.z); a.w = fmaf(w.w, hv.w, a.w);
            }
            out[((size_t)b * SN + s) * VN + t] = obr + (a.x + a.y) + (a.z + a.w);
        }
        __syncthreads();
    }
}

extern "C" void kernel_launch(void* const* d_in, const int* in_sizes, int n_in,
                              void* d_out, int out_size) {
    const int*   x        = (const int*)  d_in[0];
    const float* emb      = (const float*)d_in[1];
    const float* W_ih     = (const float*)d_in[2];
    const float* W_hh     = (const float*)d_in[3];
    const float* b_ih     = (const float*)d_in[4];
    const float* b_hh     = (const float*)d_in[5];
    const float* key_W    = (const float*)d_in[6];
    const float* key_b    = (const float*)d_in[7];
    const float* beta_W   = (const float*)d_in[8];
    const float* beta_b   = (const float*)d_in[9];
    const float* gate_W   = (const float*)d_in[10];
    const float* gate_b   = (const float*)d_in[11];
    const float* shift_W  = (const float*)d_in[12];
    const float* shift_b  = (const float*)d_in[13];
    const float* gamma_W  = (const float*)d_in[14];
    const float* gamma_b  = (const float*)d_in[15];
    const float* erase_W  = (const float*)d_in[16];
    const float* erase_b  = (const float*)d_in[17];
    const float* add_W    = (const float*)d_in[18];
    const float* add_b    = (const float*)d_in[19];
    const float* out_W    = (const float*)d_in[20];
    const float* out_b    = (const float*)d_in[21];
    const float* mem_init = (const float*)d_in[22];
    float* out = (float*)d_out;

    int prep_blocks = (NP_TOTAL + 255) / 256;
    prep_kernel<<<prep_blocks, 256>>>(
        W_ih, W_hh, b_ih, b_hh,
        key_W, key_b, beta_W, beta_b, gate_W, gate_b,
        shift_W, shift_b, gamma_W, gamma_b,
        erase_W, erase_b, add_W, add_b, out_W);

    size_t smem_bytes = SMEM_FLOATS * sizeof(float);
    cudaFuncSetAttribute(ntm_kernel, cudaFuncAttributeMaxDynamicSharedMemorySize,
                         (int)smem_bytes);
    ntm_kernel<<<BN, NT, smem_bytes>>>(x, emb, out_b, mem_init, out);
}

// round 6
// speedup vs baseline: 5.2939x; 1.2647x over previous
#include <cuda_runtime.h>
#include <math.h>

// Problem constants
#define BN 64
#define SN 128
#define DN 128
#define VN 512
#define CN 256
#define NNM 256   // memory slots N
#define MN 64     // memory width M
#define NT 512    // threads per CTA

#define KG 448            // gates GEMV k (192 + 256)
#define KG4 (KG/4)        // 112
#define KH4 (CN/4)        // 64
#define KO 320            // out GEMV k (256 + 64)
#define KO4 (KO/4)        // 80
#define NHEAD 198

// Transposed weight panels (filled by prep kernel each launch)
__device__ float4 g_Wg[KG4 * 1024];    // gates:  [kk][row]
__device__ float4 g_Wh[KH4 * NHEAD];   // heads:  [kk][row]
__device__ float4 g_Wo[KO4 * VN];      // out:    [kk][row]
__device__ float  g_gb[1024];          // b_ih + b_hh
__device__ float  g_hb[NHEAD];         // head biases
// Recurrent trace: [h(256)|rv(64)] per (b,s) for the deferred out-projection
__device__ float4 g_hrv[BN * SN * KO4];

// ---------------- SMEM layout (float offsets) ----------------
#define MEM_OFF   0
#define MEM_STR   65
#define AV_OFF    16640   // [ci(192) | h(256) | rv(64)] = 512 floats
#define AV_CI     (AV_OFF)
#define AV_RVIN   (AV_OFF + 128)
#define AV_H      (AV_OFF + 192)
#define AV_RV     (AV_OFF + 448)
#define C_OFF     17152
#define G_OFF     17408
#define KEY_OFF   18432
#define ER_OFF    18496
#define AD_OFF    18560
#define RW_OFF    18624
#define WG_OFF    18880
#define WW_OFF    19136
#define RED_OFF   19392
#define SCAL_OFF  19412
#define SMEM_FLOATS 19424
// scal indices
#define SC_BETA 0
#define SC_GATE 1
#define SC_GAMMA 2
#define SC_SH0 3
#define SC_SH1 4
#define SC_SH2 5
#define SC_KN 6

__device__ __forceinline__ float sigf(float x) { return 1.0f / (1.0f + expf(-x)); }
__device__ __forceinline__ float softplusf(float x) {
    return fmaxf(x, 0.0f) + log1pf(expf(-fabsf(x)));
}

__device__ __forceinline__ float blockReduceSum(float v, float* red) {
    #pragma unroll
    for (int o = 16; o; o >>= 1) v += __shfl_down_sync(0xffffffffu, v, o);
    int wid = threadIdx.x >> 5, lane = threadIdx.x & 31;
    __syncthreads();
    if (lane == 0) red[wid] = v;
    __syncthreads();
    if (wid == 0) {
        v = (lane < (NT / 32)) ? red[lane] : 0.0f;
        #pragma unroll
        for (int o = 8; o; o >>= 1) v += __shfl_down_sync(0xffffffffu, v, o);
        if (lane == 0) red[0] = v;
    }
    __syncthreads();
    return red[0];
}

__device__ __forceinline__ float blockReduceMax(float v, float* red) {
    #pragma unroll
    for (int o = 16; o; o >>= 1) v = fmaxf(v, __shfl_down_sync(0xffffffffu, v, o));
    int wid = threadIdx.x >> 5, lane = threadIdx.x & 31;
    __syncthreads();
    if (lane == 0) red[wid] = v;
    __syncthreads();
    if (wid == 0) {
        v = (lane < (NT / 32)) ? red[lane] : -INFINITY;
        #pragma unroll
        for (int o = 8; o; o >>= 1) v = fmaxf(v, __shfl_down_sync(0xffffffffu, v, o));
        if (lane == 0) red[0] = v;
    }
    __syncthreads();
    return red[0];
}

// ================= prep: build transposed weight panels =================
#define NP_WG (KG4 * 1024)
#define NP_WH (KH4 * NHEAD)
#define NP_WO (KO4 * VN)
#define NP_GB 1024
#define NP_HB NHEAD
#define NP_TOTAL (NP_WG + NP_WH + NP_WO + NP_GB + NP_HB)

__global__ void prep_kernel(
    const float* __restrict__ W_ih, const float* __restrict__ W_hh,
    const float* __restrict__ b_ih, const float* __restrict__ b_hh,
    const float* __restrict__ key_W, const float* __restrict__ key_b,
    const float* __restrict__ beta_W, const float* __restrict__ beta_b,
    const float* __restrict__ gate_W, const float* __restrict__ gate_b,
    const float* __restrict__ shift_W, const float* __restrict__ shift_b,
    const float* __restrict__ gamma_W, const float* __restrict__ gamma_b,
    const float* __restrict__ erase_W, const float* __restrict__ erase_b,
    const float* __restrict__ add_W, const float* __restrict__ add_b,
    const float* __restrict__ out_W)
{
    int idx = blockIdx.x * blockDim.x + threadIdx.x;
    if (idx < NP_WG) {
        int kk = idx >> 10, j = idx & 1023;
        int k = kk * 4;
        float4 v;
        if (k < 192) v = *(const float4*)(W_ih + j * 192 + k);
        else         v = *(const float4*)(W_hh + j * 256 + (k - 192));
        g_Wg[idx] = v;
        return;
    }
    idx -= NP_WG;
    if (idx < NP_WH) {
        int kk = idx / NHEAD, j = idx % NHEAD;
        const float* wr;
        if (j < 64)        wr = key_W   + j * CN;
        else if (j == 64)  wr = beta_W;
        else if (j == 65)  wr = gate_W;
        else if (j < 69)   wr = shift_W + (j - 66) * CN;
        else if (j == 69)  wr = gamma_W;
        else if (j < 134)  wr = erase_W + (j - 70) * CN;
        else               wr = add_W   + (j - 134) * CN;
        g_Wh[idx] = *(const float4*)(wr + kk * 4);
        return;
    }
    idx -= NP_WH;
    if (idx < NP_WO) {
        int kk = idx >> 9, j = idx & 511;
        g_Wo[idx] = *(const float4*)(out_W + j * KO + kk * 4);
        return;
    }
    idx -= NP_WO;
    if (idx < NP_GB) { g_gb[idx] = b_ih[idx] + b_hh[idx]; return; }
    idx -= NP_GB;
    if (idx < NP_HB) {
        int j = idx;
        float bias;
        if (j < 64)        bias = key_b[j];
        else if (j == 64)  bias = beta_b[0];
        else if (j == 65)  bias = gate_b[0];
        else if (j < 69)   bias = shift_b[j - 66];
        else if (j == 69)  bias = gamma_b[0];
        else if (j < 134)  bias = erase_b[j - 70];
        else               bias = add_b[j - 134];
        g_hb[j] = bias;
    }
}

// ================= main persistent kernel: 1 CTA per batch =================
extern __shared__ float sm[];

__global__ void __launch_bounds__(NT, 1) ntm_kernel(
    const int*   __restrict__ x,
    const float* __restrict__ emb,
    const float* __restrict__ mem_init)
{
    const int t = threadIdx.x;
    const int b = blockIdx.x;

    // ---- init state ----
    for (int i = t; i < NNM * MN; i += NT) {
        int n = i >> 6, m = i & 63;
        sm[MEM_OFF + n * MEM_STR + m] = mem_init[(b * NNM + n) * MN + m];
    }
    for (int i = t; i < 512; i += NT) sm[AV_OFF + i] = 0.0f;
    for (int i = t; i < CN; i += NT) sm[C_OFF + i] = 0.0f;
    for (int i = t; i < NNM; i += NT) sm[RW_OFF + i] = 0.0f;
    __syncthreads();

    const float gb0 = g_gb[t];
    const float gb1 = g_gb[t + 512];
    float hbr = 0.0f;
    if (t < NHEAD) hbr = g_hb[t];

    for (int s = 0; s < SN; s++) {
        // ---- A: build ci = [emb[x], rv_prev] ----
        if (t < MN) {
            sm[AV_RVIN + t] = sm[AV_RV + t];
        } else if (t >= 64 && t < 64 + DN) {
            int tt = t - 64;
            int xi = x[b * SN + s];
            sm[AV_CI + tt] = emb[xi * DN + tt];
        }
        __syncthreads();

        // ---- B: gates GEMV, 16 LDG.128 in flight per thread per block of 8 kk ----
        {
            const float4* av4 = (const float4*)(sm + AV_OFF);
            float4 a0 = make_float4(0.f, 0.f, 0.f, 0.f);
            float4 a1 = make_float4(0.f, 0.f, 0.f, 0.f);
            #pragma unroll 1
            for (int kb = 0; kb < KG4; kb += 8) {
                const float4* p = &g_Wg[kb * 1024 + t];
                float4 w0[8], w1[8];
                #pragma unroll
                for (int u = 0; u < 8; u++) { w0[u] = p[u * 1024]; w1[u] = p[u * 1024 + 512]; }
                #pragma unroll
                for (int u = 0; u < 8; u++) {
                    float4 av = av4[kb + u];
                    a0.x = fmaf(w0[u].x, av.x, a0.x); a0.y = fmaf(w0[u].y, av.y, a0.y);
                    a0.z = fmaf(w0[u].z, av.z, a0.z); a0.w = fmaf(w0[u].w, av.w, a0.w);
                    a1.x = fmaf(w1[u].x, av.x, a1.x); a1.y = fmaf(w1[u].y, av.y, a1.y);
                    a1.z = fmaf(w1[u].z, av.z, a1.z); a1.w = fmaf(w1[u].w, av.w, a1.w);
                }
            }
            sm[G_OFF + t]       = gb0 + (a0.x + a0.y) + (a0.z + a0.w);
            sm[G_OFF + 512 + t] = gb1 + (a1.x + a1.y) + (a1.z + a1.w);
        }
        __syncthreads();

        // ---- C: LSTM pointwise (torch order i,f,g,o) ----
        if (t < CN) {
            float ig = sm[G_OFF + t];
            float fg = sm[G_OFF + CN + t];
            float gg = sm[G_OFF + 2 * CN + t];
            float og = sm[G_OFF + 3 * CN + t];
            float cc = sigf(fg) * sm[C_OFF + t] + sigf(ig) * tanhf(gg);
            sm[C_OFF + t] = cc;
            sm[AV_H + t] = sigf(og) * tanhf(cc);
        }
        __syncthreads();

        // ---- D: head projections (198 rows x 256), 8 LDG in flight ----
        if (t < NHEAD) {
            const float4* h4 = (const float4*)(sm + AV_H);
            float4 a = make_float4(0.f, 0.f, 0.f, 0.f);
            #pragma unroll 1
            for (int kb = 0; kb < KH4; kb += 8) {
                const float4* p = &g_Wh[kb * NHEAD + t];
                float4 w[8];
                #pragma unroll
                for (int u = 0; u < 8; u++) w[u] = p[u * NHEAD];
                #pragma unroll
                for (int u = 0; u < 8; u++) {
                    float4 hv = h4[kb + u];
                    a.x = fmaf(w[u].x, hv.x, a.x); a.y = fmaf(w[u].y, hv.y, a.y);
                    a.z = fmaf(w[u].z, hv.z, a.z); a.w = fmaf(w[u].w, hv.w, a.w);
                }
            }
            float acc = hbr + (a.x + a.y) + (a.z + a.w);
            if (t < 64)        sm[KEY_OFF + t] = acc;
            else if (t == 64)  sm[SCAL_OFF + SC_BETA]  = softplusf(acc);
            else if (t == 65)  sm[SCAL_OFF + SC_GATE]  = sigf(acc);
            else if (t < 69)   sm[SCAL_OFF + SC_SH0 + (t - 66)] = acc;
            else if (t == 69)  sm[SCAL_OFF + SC_GAMMA] = 1.0f + softplusf(acc);
            else if (t < 134)  sm[ER_OFF + (t - 70)]  = sigf(acc);
            else               sm[AD_OFF + (t - 134)] = tanhf(acc);
        }
        __syncthreads();

        // ---- D2: key norm (warp 0) + shift softmax (thread 32) ----
        if (t < 32) {
            float k0 = sm[KEY_OFF + t], k1 = sm[KEY_OFF + t + 32];
            float sq = k0 * k0 + k1 * k1;
            #pragma unroll
            for (int o = 16; o; o >>= 1) sq += __shfl_down_sync(0xffffffffu, sq, o);
            if (t == 0) sm[SCAL_OFF + SC_KN] = fmaxf(sqrtf(sq), 1e-12f);
        } else if (t == 32) {
            float a0 = sm[SCAL_OFF + SC_SH0], a1 = sm[SCAL_OFF + SC_SH1], a2 = sm[SCAL_OFF + SC_SH2];
            float mx = fmaxf(a0, fmaxf(a1, a2));
            float e0 = expf(a0 - mx), e1 = expf(a1 - mx), e2 = expf(a2 - mx);
            float si = e0 + e1 + e2;
            sm[SCAL_OFF + SC_SH0] = e0 / si;
            sm[SCAL_OFF + SC_SH1] = e1 / si;
            sm[SCAL_OFF + SC_SH2] = e2 / si;
        }
        __syncthreads();

        // ---- E: content addressing + gate + shift + sharpen ----
        {
            float beta  = sm[SCAL_OFF + SC_BETA];
            float gate  = sm[SCAL_OFF + SC_GATE];
            float gamma = sm[SCAL_OFF + SC_GAMMA];
            float kn    = sm[SCAL_OFF + SC_KN];
            float a = -INFINITY;
            if (t < NNM) {
                float dot = 0.0f, nrm = 0.0f;
                #pragma unroll 8
                for (int m = 0; m < MN; m++) {
                    float mv = sm[MEM_OFF + t * MEM_STR + m];
                    dot = fmaf(mv, sm[KEY_OFF + m], dot);
                    nrm = fmaf(mv, mv, nrm);
                }
                float sim = dot / (fmaxf(sqrtf(nrm), 1e-12f) * kn);
                a = beta * sim;
            }
            float amax = blockReduceMax(a, sm + RED_OFF);
            float e = (t < NNM) ? expf(a - amax) : 0.0f;
            float denom = blockReduceSum(e, sm + RED_OFF);
            if (t < NNM) {
                sm[WG_OFF + t] = gate * (e / denom) + (1.0f - gate) * sm[RW_OFF + t];
            }
            __syncthreads();
            float sh0 = sm[SCAL_OFF + SC_SH0];
            float sh1 = sm[SCAL_OFF + SC_SH1];
            float sh2 = sm[SCAL_OFF + SC_SH2];
            float ws = 0.0f;
            if (t < NNM) {
                float wv = sh0 * sm[WG_OFF + ((t + 1) & 255)]
                         + sh1 * sm[WG_OFF + t]
                         + sh2 * sm[WG_OFF + ((t + 255) & 255)];
                ws = powf(wv, gamma);
            }
            float wsum = blockReduceSum(ws, sm + RED_OFF);
            if (t < NNM) {
                float wn = ws / wsum;
                sm[WW_OFF + t] = wn;
                sm[RW_OFF + t] = wn;
            }
        }
        __syncthreads();

        // ---- F: rv = w @ mem (read BEFORE write) ----
        {
            int m = t >> 3, r = t & 7;
            float acc = 0.0f;
            for (int n = r; n < NNM; n += 8)
                acc = fmaf(sm[WW_OFF + n], sm[MEM_OFF + n * MEM_STR + m], acc);
            #pragma unroll
            for (int o = 4; o; o >>= 1) acc += __shfl_down_sync(0xffffffffu, acc, o, 8);
            if (r == 0) sm[AV_RV + m] = acc;
        }
        __syncthreads();

        // ---- store [h|rv] trace for deferred out-projection (float4) ----
        if (t < KO4) g_hrv[((size_t)b * SN + s) * KO4 + t] =
            ((const float4*)(sm + AV_H))[t];

        // ---- mem update ----
        for (int i = t; i < NNM * MN; i += NT) {
            int n = i >> 6, m = i & 63;
            float wv = sm[WW_OFF + n];
            float* p = &sm[MEM_OFF + n * MEM_STR + m];
            *p = (*p) * (1.0f - wv * sm[ER_OFF + m]) + wv * sm[AD_OFF + m];
        }
        // no trailing sync needed: next-iter phase A touches disjoint smem and
        // its own barrier orders mem/hrv writes before any later reader.
    }
}

// ================= deferred out-projection GEMM =================
// out[row, col] = hrv[row, :] . Wo[col, :] + out_b[col], rows = B*S = 8192
#define OROWS 32
__global__ void __launch_bounds__(NT) ntm_out_kernel(
    const float* __restrict__ out_b, float* __restrict__ out)
{
    __shared__ float4 sh4[OROWS * KO4];   // 32 rows x 320 floats = 40KB
    const int t = threadIdx.x;
    const int r0 = blockIdx.x * OROWS;

    const float4* src = g_hrv + (size_t)r0 * KO4;
    #pragma unroll
    for (int i = t; i < OROWS * KO4; i += NT) sh4[i] = src[i];
    __syncthreads();

    float acc[OROWS];
    #pragma unroll
    for (int r = 0; r < OROWS; r++) acc[r] = 0.0f;

    #pragma unroll 2
    for (int kk = 0; kk < KO4; kk++) {
        float4 w = g_Wo[kk * VN + t];
        #pragma unroll
        for (int r = 0; r < OROWS; r++) {
            float4 hv = sh4[r * KO4 + kk];
            acc[r] = fmaf(w.x, hv.x, acc[r]);
            acc[r] = fmaf(w.y, hv.y, acc[r]);
            acc[r] = fmaf(w.z, hv.z, acc[r]);
            acc[r] = fmaf(w.w, hv.w, acc[r]);
        }
    }
    float bias = out_b[t];
    #pragma unroll
    for (int r = 0; r < OROWS; r++)
        out[(size_t)(r0 + r) * VN + t] = bias + acc[r];
}

extern "C" void kernel_launch(void* const* d_in, const int* in_sizes, int n_in,
                              void* d_out, int out_size) {
    const int*   x        = (const int*)  d_in[0];
    const float* emb      = (const float*)d_in[1];
    const float* W_ih     = (const float*)d_in[2];
    const float* W_hh     = (const float*)d_in[3];
    const float* b_ih     = (const float*)d_in[4];
    const float* b_hh     = (const float*)d_in[5];
    const float* key_W    = (const float*)d_in[6];
    const float* key_b    = (const float*)d_in[7];
    const float* beta_W   = (const float*)d_in[8];
    const float* beta_b   = (const float*)d_in[9];
    const float* gate_W   = (const float*)d_in[10];
    const float* gate_b   = (const float*)d_in[11];
    const float* shift_W  = (const float*)d_in[12];
    const float* shift_b  = (const float*)d_in[13];
    const float* gamma_W  = (const float*)d_in[14];
    const float* gamma_b  = (const float*)d_in[15];
    const float* erase_W  = (const float*)d_in[16];
    const float* erase_b  = (const float*)d_in[17];
    const float* add_W    = (const float*)d_in[18];
    const float* add_b    = (const float*)d_in[19];
    const float* out_W    = (const float*)d_in[20];
    const float* out_b    = (const float*)d_in[21];
    const float* mem_init = (const float*)d_in[22];
    float* out = (float*)d_out;

    int prep_blocks = (NP_TOTAL + 255) / 256;
    prep_kernel<<<prep_blocks, 256>>>(
        W_ih, W_hh, b_ih, b_hh,
        key_W, key_b, beta_W, beta_b, gate_W, gate_b,
        shift_W, shift_b, gamma_W, gamma_b,
        erase_W, erase_b, add_W, add_b, out_W);

    size_t smem_bytes = SMEM_FLOATS * sizeof(float);
    cudaFuncSetAttribute(ntm_kernel, cudaFuncAttributeMaxDynamicSharedMemorySize,
                         (int)smem_bytes);
    ntm_kernel<<<BN, NT, smem_bytes>>>(x, emb, mem_init);

    ntm_out_kernel<<<(BN * SN) / OROWS, NT>>>(out_b, out);
}

// round 7
// speedup vs baseline: 6.5513x; 1.2375x over previous
#include <cuda_runtime.h>
#include <cuda_fp16.h>
#include <math.h>

// Problem constants
#define BN 64
#define SN 128
#define DN 128
#define VN 512
#define CN 256
#define NNM 256   // memory slots N
#define MN 64     // memory width M
#define NT 512    // threads per CTA

#define KG 448            // gates GEMV k (192 + 256)
#define KG8 (KG/8)        // 56
#define KH8 (CN/8)        // 32
#define KO 320            // out GEMV k (256 + 64)
#define KO4 (KO/4)        // 80
#define NHEAD 198

struct __align__(16) h8 { __half2 a, b, c, d; };   // 8 halves = 16B

// Weight panels (filled by prep kernel each launch)
__device__ h8     g_Wgh[KG8 * 1024];   // gates fp16: [g][row], 0.92MB
__device__ h8     g_Whh[KH8 * NHEAD];  // heads fp16: [g][row]
__device__ float4 g_Wo[KO4 * VN];      // out fp32:   [kk][row]
__device__ float  g_gb[1024];          // b_ih + b_hh
__device__ float  g_hb[NHEAD];         // head biases
// Recurrent trace: [h(256)|rv(64)] per (b,s) for the deferred out-projection
__device__ float4 g_hrv[BN * SN * KO4];

// ---------------- SMEM layout (float offsets) ----------------
#define MEM_OFF   0
#define MEM_STR   65
#define AV_OFF    16640   // [ci(192) | h(256) | rv(64)] = 512 floats
#define AV_CI     (AV_OFF)
#define AV_RVIN   (AV_OFF + 128)
#define AV_H      (AV_OFF + 192)
#define AV_RV     (AV_OFF + 448)
#define C_OFF     17152
#define G_OFF     17408
#define KEY_OFF   18432
#define ER_OFF    18496
#define AD_OFF    18560
#define RW_OFF    18624
#define WG_OFF    18880
#define WW_OFF    19136
#define RED_OFF   19392
#define SCAL_OFF  19412
#define XR_OFF    19420   // x row (128 ints)
#define SMEM_FLOATS 19552
// scal indices
#define SC_BETA 0
#define SC_GATE 1
#define SC_GAMMA 2
#define SC_SH0 3
#define SC_SH1 4
#define SC_SH2 5
#define SC_KN 6

__device__ __forceinline__ float sigf(float x) { return 1.0f / (1.0f + expf(-x)); }
__device__ __forceinline__ float softplusf(float x) {
    return fmaxf(x, 0.0f) + log1pf(expf(-fabsf(x)));
}

__device__ __forceinline__ float blockReduceSum(float v, float* red) {
    #pragma unroll
    for (int o = 16; o; o >>= 1) v += __shfl_down_sync(0xffffffffu, v, o);
    int wid = threadIdx.x >> 5, lane = threadIdx.x & 31;
    __syncthreads();
    if (lane == 0) red[wid] = v;
    __syncthreads();
    if (wid == 0) {
        v = (lane < (NT / 32)) ? red[lane] : 0.0f;
        #pragma unroll
        for (int o = 8; o; o >>= 1) v += __shfl_down_sync(0xffffffffu, v, o);
        if (lane == 0) red[0] = v;
    }
    __syncthreads();
    return red[0];
}

__device__ __forceinline__ float blockReduceMax(float v, float* red) {
    #pragma unroll
    for (int o = 16; o; o >>= 1) v = fmaxf(v, __shfl_down_sync(0xffffffffu, v, o));
    int wid = threadIdx.x >> 5, lane = threadIdx.x & 31;
    __syncthreads();
    if (lane == 0) red[wid] = v;
    __syncthreads();
    if (wid == 0) {
        v = (lane < (NT / 32)) ? red[lane] : -INFINITY;
        #pragma unroll
        for (int o = 8; o; o >>= 1) v = fmaxf(v, __shfl_down_sync(0xffffffffu, v, o));
        if (lane == 0) red[0] = v;
    }
    __syncthreads();
    return red[0];
}

// ================= prep: build weight panels =================
#define NP_WGH (KG8 * 1024)
#define NP_WHH (KH8 * NHEAD)
#define NP_WO  (KO4 * VN)
#define NP_GB  1024
#define NP_HB  NHEAD
#define NP_TOTAL (NP_WGH + NP_WHH + NP_WO + NP_GB + NP_HB)

__device__ __forceinline__ h8 pack8(float4 lo, float4 hi) {
    h8 r;
    r.a = __floats2half2_rn(lo.x, lo.y);
    r.b = __floats2half2_rn(lo.z, lo.w);
    r.c = __floats2half2_rn(hi.x, hi.y);
    r.d = __floats2half2_rn(hi.z, hi.w);
    return r;
}

__global__ void prep_kernel(
    const float* __restrict__ W_ih, const float* __restrict__ W_hh,
    const float* __restrict__ b_ih, const float* __restrict__ b_hh,
    const float* __restrict__ key_W, const float* __restrict__ key_b,
    const float* __restrict__ beta_W, const float* __restrict__ beta_b,
    const float* __restrict__ gate_W, const float* __restrict__ gate_b,
    const float* __restrict__ shift_W, const float* __restrict__ shift_b,
    const float* __restrict__ gamma_W, const float* __restrict__ gamma_b,
    const float* __restrict__ erase_W, const float* __restrict__ erase_b,
    const float* __restrict__ add_W, const float* __restrict__ add_b,
    const float* __restrict__ out_W)
{
    int idx = blockIdx.x * blockDim.x + threadIdx.x;
    if (idx < NP_WGH) {
        int g = idx >> 10, j = idx & 1023;
        int k = g * 8;
        float4 lo, hi;
        if (k < 192) {
            lo = *(const float4*)(W_ih + j * 192 + k);
            hi = *(const float4*)(W_ih + j * 192 + k + 4);
        } else {
            lo = *(const float4*)(W_hh + j * 256 + (k - 192));
            hi = *(const float4*)(W_hh + j * 256 + (k - 188));
        }
        g_Wgh[idx] = pack8(lo, hi);
        return;
    }
    idx -= NP_WGH;
    if (idx < NP_WHH) {
        int g = idx / NHEAD, j = idx % NHEAD;
        const float* wr;
        if (j < 64)        wr = key_W   + j * CN;
        else if (j == 64)  wr = beta_W;
        else if (j == 65)  wr = gate_W;
        else if (j < 69)   wr = shift_W + (j - 66) * CN;
        else if (j == 69)  wr = gamma_W;
        else if (j < 134)  wr = erase_W + (j - 70) * CN;
        else               wr = add_W   + (j - 134) * CN;
        int k = g * 8;
        float4 lo = *(const float4*)(wr + k);
        float4 hi = *(const float4*)(wr + k + 4);
        g_Whh[idx] = pack8(lo, hi);
        return;
    }
    idx -= NP_WHH;
    if (idx < NP_WO) {
        int kk = idx >> 9, j = idx & 511;
        g_Wo[idx] = *(const float4*)(out_W + j * KO + kk * 4);
        return;
    }
    idx -= NP_WO;
    if (idx < NP_GB) { g_gb[idx] = b_ih[idx] + b_hh[idx]; return; }
    idx -= NP_GB;
    if (idx < NP_HB) {
        int j = idx;
        float bias;
        if (j < 64)        bias = key_b[j];
        else if (j == 64)  bias = beta_b[0];
        else if (j == 65)  bias = gate_b[0];
        else if (j < 69)   bias = shift_b[j - 66];
        else if (j == 69)  bias = gamma_b[0];
        else if (j < 134)  bias = erase_b[j - 70];
        else               bias = add_b[j - 134];
        g_hb[j] = bias;
    }
}

// ================= main persistent kernel: 1 CTA per batch =================
extern __shared__ float sm[];

__global__ void __launch_bounds__(NT, 1) ntm_kernel(
    const int*   __restrict__ x,
    const float* __restrict__ emb,
    const float* __restrict__ mem_init)
{
    const int t = threadIdx.x;
    const int b = blockIdx.x;

    // ---- init state ----
    for (int i = t; i < NNM * MN; i += NT) {
        int n = i >> 6, m = i & 63;
        sm[MEM_OFF + n * MEM_STR + m] = mem_init[(b * NNM + n) * MN + m];
    }
    for (int i = t; i < 512; i += NT) sm[AV_OFF + i] = 0.0f;
    for (int i = t; i < CN; i += NT) sm[C_OFF + i] = 0.0f;
    for (int i = t; i < NNM; i += NT) sm[RW_OFF + i] = 0.0f;
    if (t < SN) ((int*)sm)[XR_OFF + t] = x[b * SN + t];
    __syncthreads();

    const float gb0 = g_gb[t];
    const float gb1 = g_gb[t + 512];
    float hbr = 0.0f;
    if (t < NHEAD) hbr = g_hb[t];

    for (int s = 0; s < SN; s++) {
        // ---- A: build ci = [emb[x], rv_prev] ----
        if (t < MN) {
            sm[AV_RVIN + t] = sm[AV_RV + t];
        } else if (t >= 64 && t < 64 + DN) {
            int tt = t - 64;
            int xi = ((int*)sm)[XR_OFF + s];
            sm[AV_CI + tt] = emb[xi * DN + tt];
        }
        __syncthreads();

        // ---- B: gates GEMV (fp16 weights, fp32 accum), 8 LDG.128 in flight ----
        {
            const float4* av4 = (const float4*)(sm + AV_OFF);
            float4 a0 = make_float4(0.f, 0.f, 0.f, 0.f);
            float4 a1 = make_float4(0.f, 0.f, 0.f, 0.f);
            #pragma unroll 1
            for (int kb = 0; kb < KG8; kb += 4) {
                const h8* p = &g_Wgh[kb * 1024 + t];
                h8 w0[4], w1[4];
                #pragma unroll
                for (int u = 0; u < 4; u++) { w0[u] = p[u * 1024]; w1[u] = p[u * 1024 + 512]; }
                #pragma unroll
                for (int u = 0; u < 4; u++) {
                    float4 av0 = av4[(kb + u) * 2];
                    float4 av1 = av4[(kb + u) * 2 + 1];
                    float2 f;
                    f = __half22float2(w0[u].a); a0.x = fmaf(f.x, av0.x, a0.x); a0.y = fmaf(f.y, av0.y, a0.y);
                    f = __half22float2(w0[u].b); a0.z = fmaf(f.x, av0.z, a0.z); a0.w = fmaf(f.y, av0.w, a0.w);
                    f = __half22float2(w0[u].c); a0.x = fmaf(f.x, av1.x, a0.x); a0.y = fmaf(f.y, av1.y, a0.y);
                    f = __half22float2(w0[u].d); a0.z = fmaf(f.x, av1.z, a0.z); a0.w = fmaf(f.y, av1.w, a0.w);
                    f = __half22float2(w1[u].a); a1.x = fmaf(f.x, av0.x, a1.x); a1.y = fmaf(f.y, av0.y, a1.y);
                    f = __half22float2(w1[u].b); a1.z = fmaf(f.x, av0.z, a1.z); a1.w = fmaf(f.y, av0.w, a1.w);
                    f = __half22float2(w1[u].c); a1.x = fmaf(f.x, av1.x, a1.x); a1.y = fmaf(f.y, av1.y, a1.y);
                    f = __half22float2(w1[u].d); a1.z = fmaf(f.x, av1.z, a1.z); a1.w = fmaf(f.y, av1.w, a1.w);
                }
            }
            sm[G_OFF + t]       = gb0 + (a0.x + a0.y) + (a0.z + a0.w);
            sm[G_OFF + 512 + t] = gb1 + (a1.x + a1.y) + (a1.z + a1.w);
        }
        __syncthreads();

        // ---- C: LSTM pointwise (torch order i,f,g,o) ----
        if (t < CN) {
            float ig = sm[G_OFF + t];
            float fg = sm[G_OFF + CN + t];
            float gg = sm[G_OFF + 2 * CN + t];
            float og = sm[G_OFF + 3 * CN + t];
            float cc = sigf(fg) * sm[C_OFF + t] + sigf(ig) * tanhf(gg);
            sm[C_OFF + t] = cc;
            sm[AV_H + t] = sigf(og) * tanhf(cc);
        }
        __syncthreads();

        // ---- D: head projections (198 rows x 256), fp16 weights ----
        if (t < NHEAD) {
            const float4* h4 = (const float4*)(sm + AV_H);
            float4 a = make_float4(0.f, 0.f, 0.f, 0.f);
            #pragma unroll 1
            for (int kb = 0; kb < KH8; kb += 4) {
                const h8* p = &g_Whh[kb * NHEAD + t];
                h8 w[4];
                #pragma unroll
                for (int u = 0; u < 4; u++) w[u] = p[u * NHEAD];
                #pragma unroll
                for (int u = 0; u < 4; u++) {
                    float4 hv0 = h4[(kb + u) * 2];
                    float4 hv1 = h4[(kb + u) * 2 + 1];
                    float2 f;
                    f = __half22float2(w[u].a); a.x = fmaf(f.x, hv0.x, a.x); a.y = fmaf(f.y, hv0.y, a.y);
                    f = __half22float2(w[u].b); a.z = fmaf(f.x, hv0.z, a.z); a.w = fmaf(f.y, hv0.w, a.w);
                    f = __half22float2(w[u].c); a.x = fmaf(f.x, hv1.x, a.x); a.y = fmaf(f.y, hv1.y, a.y);
                    f = __half22float2(w[u].d); a.z = fmaf(f.x, hv1.z, a.z); a.w = fmaf(f.y, hv1.w, a.w);
                }
            }
            float acc = hbr + (a.x + a.y) + (a.z + a.w);
            if (t < 64)        sm[KEY_OFF + t] = acc;
            else if (t == 64)  sm[SCAL_OFF + SC_BETA]  = softplusf(acc);
            else if (t == 65)  sm[SCAL_OFF + SC_GATE]  = sigf(acc);
            else if (t < 69)   sm[SCAL_OFF + SC_SH0 + (t - 66)] = acc;
            else if (t == 69)  sm[SCAL_OFF + SC_GAMMA] = 1.0f + softplusf(acc);
            else if (t < 134)  sm[ER_OFF + (t - 70)]  = sigf(acc);
            else               sm[AD_OFF + (t - 134)] = tanhf(acc);
        }
        __syncthreads();

        // ---- D2: key norm (warp 0) + shift softmax (thread 32) ----
        if (t < 32) {
            float k0 = sm[KEY_OFF + t], k1 = sm[KEY_OFF + t + 32];
            float sq = k0 * k0 + k1 * k1;
            #pragma unroll
            for (int o = 16; o; o >>= 1) sq += __shfl_down_sync(0xffffffffu, sq, o);
            if (t == 0) sm[SCAL_OFF + SC_KN] = fmaxf(sqrtf(sq), 1e-12f);
        } else if (t == 32) {
            float a0 = sm[SCAL_OFF + SC_SH0], a1 = sm[SCAL_OFF + SC_SH1], a2 = sm[SCAL_OFF + SC_SH2];
            float mx = fmaxf(a0, fmaxf(a1, a2));
            float e0 = expf(a0 - mx), e1 = expf(a1 - mx), e2 = expf(a2 - mx);
            float si = e0 + e1 + e2;
            sm[SCAL_OFF + SC_SH0] = e0 / si;
            sm[SCAL_OFF + SC_SH1] = e1 / si;
            sm[SCAL_OFF + SC_SH2] = e2 / si;
        }
        __syncthreads();

        // ---- E: content addressing + gate + shift + sharpen ----
        {
            float beta  = sm[SCAL_OFF + SC_BETA];
            float gate  = sm[SCAL_OFF + SC_GATE];
            float gamma = sm[SCAL_OFF + SC_GAMMA];
            float kn    = sm[SCAL_OFF + SC_KN];
            float a = -INFINITY;
            if (t < NNM) {
                float dot = 0.0f, nrm = 0.0f;
                #pragma unroll 8
                for (int m = 0; m < MN; m++) {
                    float mv = sm[MEM_OFF + t * MEM_STR + m];
                    dot = fmaf(mv, sm[KEY_OFF + m], dot);
                    nrm = fmaf(mv, mv, nrm);
                }
                float sim = dot / (fmaxf(sqrtf(nrm), 1e-12f) * kn);
                a = beta * sim;
            }
            float amax = blockReduceMax(a, sm + RED_OFF);
            float e = (t < NNM) ? expf(a - amax) : 0.0f;
            float denom = blockReduceSum(e, sm + RED_OFF);
            if (t < NNM) {
                sm[WG_OFF + t] = gate * (e / denom) + (1.0f - gate) * sm[RW_OFF + t];
            }
            __syncthreads();
            float sh0 = sm[SCAL_OFF + SC_SH0];
            float sh1 = sm[SCAL_OFF + SC_SH1];
            float sh2 = sm[SCAL_OFF + SC_SH2];
            float ws = 0.0f;
            if (t < NNM) {
                float wv = sh0 * sm[WG_OFF + ((t + 1) & 255)]
                         + sh1 * sm[WG_OFF + t]
                         + sh2 * sm[WG_OFF + ((t + 255) & 255)];
                ws = powf(wv, gamma);
            }
            float wsum = blockReduceSum(ws, sm + RED_OFF);
            if (t < NNM) {
                float wn = ws / wsum;
                sm[WW_OFF + t] = wn;
                sm[RW_OFF + t] = wn;
            }
        }
        __syncthreads();

        // ---- F: rv = w @ mem (read BEFORE write) ----
        {
            int m = t >> 3, r = t & 7;
            float acc = 0.0f;
            for (int n = r; n < NNM; n += 8)
                acc = fmaf(sm[WW_OFF + n], sm[MEM_OFF + n * MEM_STR + m], acc);
            #pragma unroll
            for (int o = 4; o; o >>= 1) acc += __shfl_down_sync(0xffffffffu, acc, o, 8);
            if (r == 0) sm[AV_RV + m] = acc;
        }
        __syncthreads();

        // ---- store [h|rv] trace for deferred out-projection (float4) ----
        if (t < KO4) g_hrv[((size_t)b * SN + s) * KO4 + t] =
            ((const float4*)(sm + AV_H))[t];

        // ---- mem update ----
        for (int i = t; i < NNM * MN; i += NT) {
            int n = i >> 6, m = i & 63;
            float wv = sm[WW_OFF + n];
            float* p = &sm[MEM_OFF + n * MEM_STR + m];
            *p = (*p) * (1.0f - wv * sm[ER_OFF + m]) + wv * sm[AD_OFF + m];
        }
        // no trailing sync needed: next-iter phase A touches disjoint smem and
        // its own barrier orders mem/hrv writes before any later reader.
    }
}

// ================= deferred out-projection GEMM =================
// out[row, col] = hrv[row, :] . Wo[col, :] + out_b[col], rows = B*S = 8192
#define OROWS 32
__global__ void __launch_bounds__(NT) ntm_out_kernel(
    const float* __restrict__ out_b, float* __restrict__ out)
{
    __shared__ float4 sh4[OROWS * KO4];   // 32 rows x 320 floats = 40KB
    const int t = threadIdx.x;
    const int r0 = blockIdx.x * OROWS;

    const float4* src = g_hrv + (size_t)r0 * KO4;
    #pragma unroll
    for (int i = t; i < OROWS * KO4; i += NT) sh4[i] = src[i];
    __syncthreads();

    float acc[OROWS];
    #pragma unroll
    for (int r = 0; r < OROWS; r++) acc[r] = 0.0f;

    #pragma unroll 2
    for (int kk = 0; kk < KO4; kk++) {
        float4 w = g_Wo[kk * VN + t];
        #pragma unroll
        for (int r = 0; r < OROWS; r++) {
            float4 hv = sh4[r * KO4 + kk];
            acc[r] = fmaf(w.x, hv.x, acc[r]);
            acc[r] = fmaf(w.y, hv.y, acc[r]);
            acc[r] = fmaf(w.z, hv.z, acc[r]);
            acc[r] = fmaf(w.w, hv.w, acc[r]);
        }
    }
    float bias = out_b[t];
    #pragma unroll
    for (int r = 0; r < OROWS; r++)
        out[(size_t)(r0 + r) * VN + t] = bias + acc[r];
}

extern "C" void kernel_launch(void* const* d_in, const int* in_sizes, int n_in,
                              void* d_out, int out_size) {
    const int*   x        = (const int*)  d_in[0];
    const float* emb      = (const float*)d_in[1];
    const float* W_ih     = (const float*)d_in[2];
    const float* W_hh     = (const float*)d_in[3];
    const float* b_ih     = (const float*)d_in[4];
    const float* b_hh     = (const float*)d_in[5];
    const float* key_W    = (const float*)d_in[6];
    const float* key_b    = (const float*)d_in[7];
    const float* beta_W   = (const float*)d_in[8];
    const float* beta_b   = (const float*)d_in[9];
    const float* gate_W   = (const float*)d_in[10];
    const float* gate_b   = (const float*)d_in[11];
    const float* shift_W  = (const float*)d_in[12];
    const float* shift_b  = (const float*)d_in[13];
    const float* gamma_W  = (const float*)d_in[14];
    const float* gamma_b  = (const float*)d_in[15];
    const float* erase_W  = (const float*)d_in[16];
    const float* erase_b  = (const float*)d_in[17];
    const float* add_W    = (const float*)d_in[18];
    const float* add_b    = (const float*)d_in[19];
    const float* out_W    = (const float*)d_in[20];
    const float* out_b    = (const float*)d_in[21];
    const float* mem_init = (const float*)d_in[22];
    float* out = (float*)d_out;

    int prep_blocks = (NP_TOTAL + 255) / 256;
    prep_kernel<<<prep_blocks, 256>>>(
        W_ih, W_hh, b_ih, b_hh,
        key_W, key_b, beta_W, beta_b, gate_W, gate_b,
        shift_W, shift_b, gamma_W, gamma_b,
        erase_W, erase_b, add_W, add_b, out_W);

    size_t smem_bytes = SMEM_FLOATS * sizeof(float);
    cudaFuncSetAttribute(ntm_kernel, cudaFuncAttributeMaxDynamicSharedMemorySize,
                         (int)smem_bytes);
    ntm_kernel<<<BN, NT, smem_bytes>>>(x, emb, mem_init);

    ntm_out_kernel<<<(BN * SN) / OROWS, NT>>>(out_b, out);
}